// round 8
// baseline (speedup 1.0000x reference)
#include <cuda_runtime.h>
#include <cuda_bf16.h>
#include <stdint.h>

// qGPS: out[b] = sum_m prod_l eps[samples[b,l], m, l],  B=4096 L=256 D=2 M=64
//
// log-domain GEMM on HMMA:
//   acc[b,m] = sum_l s_l * d[m,l],  d = log2(eps1/eps0) split bf16 hi+lo
//   out[b]   = sum_m exp2(base2[m] + acc_hi[b,m] + acc_lo[b,m])
// m-dimension split across CTA pairs (sum over m is additive -> atomicAdd).
// 256 CTAs x 256 threads, 2 CTAs/SM; per CTA: 32 batches x 32 m's.

#define NB 4096
#define NL 256
#define NM 64

__device__ __align__(16) __nv_bfloat16 g_dhi[NM * NL];
__device__ __align__(16) __nv_bfloat16 g_dlo[NM * NL];
__device__ float g_base2[NM];

// ---------------- kernel 1: prep (also zeroes out) ----------------
__global__ __launch_bounds__(NL, 1) void prep_kernel(const float* __restrict__ eps,
                                                     float* __restrict__ out)
{
    __shared__ float wsum[8];
    int m = blockIdx.x, l = threadIdx.x;
    float e0 = eps[m * NL + l];
    float e1 = eps[NM * NL + m * NL + l];
    float l0 = log2f(e0);
    float d  = log2f(e1) - l0;
    __nv_bfloat16 hi = __float2bfloat16(d);
    g_dhi[m * NL + l] = hi;
    g_dlo[m * NL + l] = __float2bfloat16(d - __bfloat162float(hi));
    if (l < NB / NM) out[m * (NB / NM) + l] = 0.0f;   // zero 64 outputs per CTA
    float s = l0;
#pragma unroll
    for (int off = 16; off; off >>= 1)
        s += __shfl_xor_sync(0xffffffffu, s, off);
    if ((l & 31) == 0) wsum[l >> 5] = s;
    __syncthreads();
    if (l == 0) {
        float t = 0.0f;
#pragma unroll
        for (int j = 0; j < 8; j++) t += wsum[j];
        g_base2[m] = t;
    }
}

// ---------------- kernel 2: HMMA GEMM + exp2 epilogue ----------------
// smem: A (32 rows x 512B swz) [0,16K)  Bh [16K,32K)  Bl [32K,48K)
//       base2 [48K,+128)  part [48K+128,+512)
#define SM_A   0
#define SM_BH  16384
#define SM_BL  32768
#define SM_B2  49152
#define SM_PT  49280
#define SMEM2  49792

__device__ __forceinline__ uint32_t swz(int row, int byte_in_row) {
    return (uint32_t)(row * 512 + (byte_in_row ^ ((row & 7) << 4)));
}

__device__ __forceinline__ void mma16816(float* d, uint32_t a0, uint32_t a1,
                                         uint32_t a2, uint32_t a3,
                                         uint32_t b0, uint32_t b1)
{
    asm volatile(
        "mma.sync.aligned.m16n8k16.row.col.f32.bf16.bf16.f32 "
        "{%0,%1,%2,%3}, {%4,%5,%6,%7}, {%8,%9}, {%0,%1,%2,%3};"
        : "+f"(d[0]), "+f"(d[1]), "+f"(d[2]), "+f"(d[3])
        : "r"(a0), "r"(a1), "r"(a2), "r"(a3), "r"(b0), "r"(b1));
}

__global__ __launch_bounds__(256, 2)
void qgps_hmma_kernel(const int* __restrict__ samples, float* __restrict__ out)
{
    extern __shared__ char smem[];
    const int tid  = threadIdx.x;
    const int wid  = tid >> 5;          // 0..7
    const int lane = tid & 31;
    const int t    = blockIdx.x >> 1;   // batch tile (32 batches)
    const int h    = blockIdx.x & 1;    // m-half (32 m's)

    // ---- fill A: samples -> bf16 {0,1}, swizzled (32 rows x 256 cols) ----
    {
        const int4* src = (const int4*)(samples + (size_t)t * 32 * NL);
#pragma unroll
        for (int it = 0; it < 4; it++) {
            int c   = tid + it * 256;           // 16B chunk id, 0..1023
            int row = c >> 5;
            int cb  = (c & 31) * 16;
            int4 sa = src[2 * c], sb = src[2 * c + 1];
            uint32_t w0 = (uint32_t)sa.x * 0x3F80u + (uint32_t)sa.y * 0x3F800000u;
            uint32_t w1 = (uint32_t)sa.z * 0x3F80u + (uint32_t)sa.w * 0x3F800000u;
            uint32_t w2 = (uint32_t)sb.x * 0x3F80u + (uint32_t)sb.y * 0x3F800000u;
            uint32_t w3 = (uint32_t)sb.z * 0x3F80u + (uint32_t)sb.w * 0x3F800000u;
            *(uint4*)(smem + SM_A + swz(row, cb)) = make_uint4(w0, w1, w2, w3);
        }
    }
    // ---- fill Bh/Bl for this m-half (32 rows x 256 cols each) ----
    {
        const uint4* hs = (const uint4*)g_dhi + (size_t)h * 1024;
        const uint4* ls = (const uint4*)g_dlo + (size_t)h * 1024;
#pragma unroll
        for (int it = 0; it < 4; it++) {
            int c   = tid + it * 256;           // 0..1023
            int row = c >> 5;
            int cb  = (c & 31) * 16;
            uint32_t a = swz(row, cb);
            *(uint4*)(smem + SM_BH + a) = hs[c];
            *(uint4*)(smem + SM_BL + a) = ls[c];
        }
    }
    if (tid < 32) *(float*)(smem + SM_B2 + tid * 4) = g_base2[h * 32 + tid];
    __syncthreads();

    // ---- MMA: warp = (row tile rt = wid&1) x (8-col n tile nq = wid>>1) ----
    const int rt   = wid & 1;
    const int nq   = wid >> 1;          // 0..3 (8 cols each within this half)
    const int qrow = lane >> 2;
    const int qk   = (lane & 3) * 4;
    const int ar0  = rt * 16 + qrow;    // < 32
    const int ar1  = ar0 + 8;
    const int br   = nq * 8 + qrow;     // < 32

    float ah[4] = {0, 0, 0, 0}, al[4] = {0, 0, 0, 0};

#pragma unroll
    for (int kk = 0; kk < 16; kk++) {
        int kb = kk * 32 + qk;
        uint32_t a0 = *(const uint32_t*)(smem + SM_A + swz(ar0, kb));
        uint32_t a1 = *(const uint32_t*)(smem + SM_A + swz(ar1, kb));
        uint32_t a2 = *(const uint32_t*)(smem + SM_A + swz(ar0, kb + 16));
        uint32_t a3 = *(const uint32_t*)(smem + SM_A + swz(ar1, kb + 16));
        uint32_t bh0 = *(const uint32_t*)(smem + SM_BH + swz(br, kb));
        uint32_t bh1 = *(const uint32_t*)(smem + SM_BH + swz(br, kb + 16));
        mma16816(ah, a0, a1, a2, a3, bh0, bh1);
        uint32_t bl0 = *(const uint32_t*)(smem + SM_BL + swz(br, kb));
        uint32_t bl1 = *(const uint32_t*)(smem + SM_BL + swz(br, kb + 16));
        mma16816(al, a0, a1, a2, a3, bl0, bl1);
    }

    // ---- epilogue: exp2(acc_h + acc_l + base2), reduce this warp's 8 cols ----
    const float* b2 = (const float*)(smem + SM_B2);
    {
        int c0 = nq * 8 + (lane & 3) * 2;
        float ba = b2[c0], bb = b2[c0 + 1];
        float e0, e1, e2, e3;
        asm("ex2.approx.ftz.f32 %0, %1;" : "=f"(e0) : "f"(ah[0] + al[0] + ba));
        asm("ex2.approx.ftz.f32 %0, %1;" : "=f"(e1) : "f"(ah[1] + al[1] + bb));
        asm("ex2.approx.ftz.f32 %0, %1;" : "=f"(e2) : "f"(ah[2] + al[2] + ba));
        asm("ex2.approx.ftz.f32 %0, %1;" : "=f"(e3) : "f"(ah[3] + al[3] + bb));
        float s0 = e0 + e1;   // row qrow
        float s1 = e2 + e3;   // row qrow + 8
#pragma unroll
        for (int off = 1; off <= 2; off <<= 1) {
            s0 += __shfl_xor_sync(0xffffffffu, s0, off);
            s1 += __shfl_xor_sync(0xffffffffu, s1, off);
        }
        float* part = (float*)(smem + SM_PT);   // [32 rows][4 nq]
        if ((lane & 3) == 0) {
            part[(rt * 16 + qrow)     * 4 + nq] = s0;
            part[(rt * 16 + qrow + 8) * 4 + nq] = s1;
        }
    }
    __syncthreads();
    if (tid < 32) {
        const float* part = (const float*)(smem + SM_PT);
        float s = part[tid * 4] + part[tid * 4 + 1] + part[tid * 4 + 2] + part[tid * 4 + 3];
        atomicAdd(out + t * 32 + tid, s);
    }
}

extern "C" void kernel_launch(void* const* d_in, const int* in_sizes, int n_in,
                              void* d_out, int out_size)
{
    const int*   samples = (const int*)d_in[0];
    const float* eps     = (const float*)d_in[1];
    if (n_in >= 2 && in_sizes[0] == 2 * NM * NL && in_sizes[1] == NB * NL) {
        samples = (const int*)d_in[1];
        eps     = (const float*)d_in[0];
    }
    prep_kernel<<<NM, NL>>>(eps, (float*)d_out);
    cudaFuncSetAttribute(qgps_hmma_kernel,
                         cudaFuncAttributeMaxDynamicSharedMemorySize, SMEM2);
    qgps_hmma_kernel<<<(NB / 32) * 2, 256, SMEM2>>>(samples, (float*)d_out);
}